// round 14
// baseline (speedup 1.0000x reference)
#include <cuda_runtime.h>
#include <cstdint>

// Screen tiling constants (match reference)
#define SW 1280
#define SH 720
#define TL 16
#define NBW 80           // ceil(1280/16)
#define NBH 45           // ceil(720/16)
#define NUM_BLOCK (NBW*NBH)   // 3600
#define N_POINTS 32768
#define NWORDS (N_POINTS / 32)   // 1024 bitmask words per tile-row

// Bit-packed separable masks: bit j of word w in row r = point (w*32+j) in row r.
// Total 500 KB -> L1/L2 resident, near-zero LTS read traffic in expand.
__device__ unsigned int g_bitsX[NBW * NWORDS];   // 320 KB
__device__ unsigned int g_bitsY[NBH * NWORDS];   // 180 KB

// ---------------------------------------------------------------------------
// Phase 1: each warp owns 32 consecutive points. Each lane computes its
// point's tile-index intervals once; then 80+45 __ballot_sync's produce one
// bitmask word per row, stored by lane 0. 1024 warps, ~125 ballots each.
// ---------------------------------------------------------------------------
__global__ void build_masks_kernel(const float* __restrict__ pos2d,
                                   const float* __restrict__ radius)
{
    int n    = blockIdx.x * blockDim.x + threadIdx.x;   // point id (= lane-aligned)
    int wi   = n >> 5;                                  // global warp / word index
    int lane = n & 31;

    float px = pos2d[2 * n + 0];
    float py = pos2d[2 * n + 1];
    float r  = radius[n];

    // Match reference exactly: clip to [0, W]/[0, H] then truncate to int32.
    int xmin = (int)fminf(fmaxf(px - r, 0.0f), (float)SW);
    int xmax = (int)fminf(fmaxf(px + r, 0.0f), (float)SW);
    int ymin = (int)fminf(fmaxf(py - r, 0.0f), (float)SH);
    int ymax = (int)fminf(fmaxf(py + r, 0.0f), (float)SH);

    // Tile edges are exact multiples of 16 (no screen-edge clamping needed):
    //   in_mask <=> xi in [xmin>>4, (xmax+15)>>4)   when xmax > xmin
    int x0 = xmin >> 4;
    int x1 = (xmax + 15) >> 4;
    if (xmax <= xmin) x1 = x0;          // degenerate AABB -> empty
    int y0 = ymin >> 4;
    int y1 = (ymax + 15) >> 4;
    if (ymax <= ymin) y1 = y0;

    #pragma unroll
    for (int xi = 0; xi < NBW; xi++) {
        unsigned int w = __ballot_sync(0xffffffffu, (xi >= x0) & (xi < x1));
        if (lane == 0) g_bitsX[xi * NWORDS + wi] = w;
    }
    #pragma unroll
    for (int yi = 0; yi < NBH; yi++) {
        unsigned int w = __ballot_sync(0xffffffffu, (yi >= y0) & (yi < y1));
        if (lane == 0) g_bitsY[yi * NWORDS + wi] = w;
    }
}

// ---------------------------------------------------------------------------
// Phase 2: out[t*N + n] = float(bitX[t/45][n] & bitY[t%45][n]).
// 8 points per thread as two warp-contiguous groups of 4 (proven layout from
// R13: each STG.128 across a warp spans a contiguous 512 B). Per group: load
// the two 32-point bitmask words (8 threads broadcast-share each word in L1),
// AND, extract this thread's nibble, spread nibble -> byte mask via
// IMAD(0x00204081)+LOP3(0x01010101), then the validated PRMT+IMAD unpack to
// f32 bit patterns (0x3f800000 * bit). Streaming .cs stores.
// grid = (32768/(256*8)=16, 3600), block = 256.
// ---------------------------------------------------------------------------
__global__ void __launch_bounds__(256, 8)
expand_kernel(uint4* __restrict__ out)
{
    const int t   = blockIdx.y;               // tile id, 0..3599
    const int tid = threadIdx.x;
    const int blockBase = blockIdx.x * (256 * 8);        // first point of block
    const int n_a = blockBase + tid * 4;                 // group A point index
    const int n_b = n_a + 256 * 4;                       // group B, +1024 pts

    int xi = t / NBH;
    int yi = t - xi * NBH;
    const unsigned int* bx = &g_bitsX[xi * NWORDS];
    const unsigned int* by = &g_bitsY[yi * NWORDS];

    // Group A: word + in-word nibble shift
    unsigned int wxa = __ldg(bx + (n_a >> 5));
    unsigned int wya = __ldg(by + (n_a >> 5));
    unsigned int wxb = __ldg(bx + (n_b >> 5));
    unsigned int wyb = __ldg(by + (n_b >> 5));
    const int s = n_a & 31;                   // == n_b & 31 (1024 apart)

    unsigned int mA = ((wxa & wya) >> s) & 0xFu;   // 4 bits, pts n_a..n_a+3
    unsigned int mB = ((wxb & wyb) >> s) & 0xFu;

    // Spread nibble -> one 0x00/0x01 byte per point (same form as byte masks)
    unsigned int m0 = (mA * 0x00204081u) & 0x01010101u;
    unsigned int m1 = (mB * 0x00204081u) & 0x01010101u;

    const unsigned int ONE = 0x3f800000u;     // bit pattern of 1.0f

    uint4 o0, o1;
    o0.x = __byte_perm(m0, 0u, 0x4440) * ONE;
    o0.y = __byte_perm(m0, 0u, 0x4441) * ONE;
    o0.z = __byte_perm(m0, 0u, 0x4442) * ONE;
    o0.w = __byte_perm(m0, 0u, 0x4443) * ONE;
    o1.x = __byte_perm(m1, 0u, 0x4440) * ONE;
    o1.y = __byte_perm(m1, 0u, 0x4441) * ONE;
    o1.z = __byte_perm(m1, 0u, 0x4442) * ONE;
    o1.w = __byte_perm(m1, 0u, 0x4443) * ONE;

    const size_t rowBase = (size_t)t * (N_POINTS / 4);   // uint4 units
    __stcs(out + rowBase + (n_a >> 2), o0);   // warp-contiguous 512 B
    __stcs(out + rowBase + (n_b >> 2), o1);   // warp-contiguous 512 B
}

extern "C" void kernel_launch(void* const* d_in, const int* in_sizes, int n_in,
                              void* d_out, int out_size)
{
    const float* pos2d  = (const float*)d_in[0];
    const float* radius = (const float*)d_in[1];
    uint4* out          = (uint4*)d_out;

    build_masks_kernel<<<N_POINTS / 256, 256>>>(pos2d, radius);

    dim3 grid(N_POINTS / (256 * 8), NUM_BLOCK);   // (16, 3600)
    expand_kernel<<<grid, 256>>>(out);
}